// round 6
// baseline (speedup 1.0000x reference)
#include <cuda_runtime.h>
#include <cuda_fp16.h>

#define B_SZ   16
#define NUM_CN 25000
#define NUM_VN 50000
#define NUM_E  200000
#define D_EMB  16
#define D_HID  32
#define D_MSG  16

typedef unsigned long long ULL;

// ---- scratch (device globals) ----
__device__ __half g_hf_x[(size_t)NUM_CN * B_SZ * D_HID];   // [CN][B][32] fp16
__device__ __half g_hf_z[(size_t)NUM_CN * B_SZ * D_HID];
__device__ int      g_cnt[4 * NUM_VN];                     // deg_x|deg_z|cur_x|cur_z
__device__ int      g_incl_x[NUM_VN], g_incl_z[NUM_VN];
__device__ int      g_bsum_x[64],     g_bsum_z[64];
__device__ int      g_offs_x[NUM_VN + 1], g_offs_z[NUM_VN + 1];
__device__ unsigned g_csr_x[NUM_E],   g_csr_z[NUM_E];      // f | (mask<<16)
__device__ unsigned g_mask_x[NUM_CN], g_mask_z[NUM_CN];

// ---------------------------------------------------------------------------
// f32x2 packed helpers
__device__ __forceinline__ ULL pk2(float x) {
    ULL d; asm("mov.b64 %0, {%1, %1};" : "=l"(d) : "f"(x)); return d;
}
__device__ __forceinline__ ULL pkp(float x, float y) {
    ULL d; asm("mov.b64 %0, {%1, %2};" : "=l"(d) : "f"(x), "f"(y)); return d;
}
__device__ __forceinline__ float2 up2(ULL a) {
    float lo, hi; asm("mov.b64 {%0, %1}, %2;" : "=f"(lo), "=f"(hi) : "l"(a));
    return make_float2(lo, hi);
}
__device__ __forceinline__ ULL f2fma(ULL a, ULL b, ULL c) {
    ULL d; asm("fma.rn.f32x2 %0, %1, %2, %3;" : "=l"(d) : "l"(a), "l"(b), "l"(c));
    return d;
}

// ---------------------------------------------------------------------------
// kernel 0: degree histogram + syndrome bitmask pack
__global__ void __launch_bounds__(256) prep_kernel(
    const int* __restrict__ to_x, const int* __restrict__ to_z,
    const int* __restrict__ syn_x, const int* __restrict__ syn_z,
    int* __restrict__ deg_x, int* __restrict__ deg_z,
    unsigned* __restrict__ mask_x, unsigned* __restrict__ mask_z)
{
    int i = blockIdx.x * 256 + threadIdx.x;
    if (i < NUM_E) {
        atomicAdd(&deg_x[__ldg(to_x + i)], 1);
        atomicAdd(&deg_z[__ldg(to_z + i)], 1);
    }
    if (i < NUM_CN) {
        unsigned mx = 0, mz = 0;
        #pragma unroll
        for (int b = 0; b < B_SZ; b++) {
            mx |= (unsigned)(__ldg(syn_x + (size_t)b * NUM_CN + i) & 1) << b;
            mz |= (unsigned)(__ldg(syn_z + (size_t)b * NUM_CN + i) & 1) << b;
        }
        mask_x[i] = mx;
        mask_z[i] = mz;
    }
}

// ---------------------------------------------------------------------------
// parallel scan, polarity via blockIdx.y / blockIdx.x
__global__ void __launch_bounds__(1024) scan1_kernel(
    const int* __restrict__ deg_x, const int* __restrict__ deg_z,
    int* __restrict__ incl_x, int* __restrict__ incl_z,
    int* __restrict__ bsum_x, int* __restrict__ bsum_z)
{
    const int* deg  = blockIdx.y == 0 ? deg_x  : deg_z;
    int*       incl = blockIdx.y == 0 ? incl_x : incl_z;
    int*       bsum = blockIdx.y == 0 ? bsum_x : bsum_z;
    __shared__ int s[1024];
    int t = threadIdx.x;
    int gid = blockIdx.x * 1024 + t;
    s[t] = (gid < NUM_VN) ? deg[gid] : 0;
    __syncthreads();
    #pragma unroll
    for (int off = 1; off < 1024; off <<= 1) {
        int x = (t >= off) ? s[t - off] : 0;
        __syncthreads();
        s[t] += x;
        __syncthreads();
    }
    if (gid < NUM_VN) incl[gid] = s[t];
    if (t == 1023) bsum[blockIdx.x] = s[t];
}

__global__ void __launch_bounds__(64) scan2_kernel(int* bsum_x, int* bsum_z, int nb)
{
    int* bs = blockIdx.x == 0 ? bsum_x : bsum_z;
    __shared__ int s[64];
    int t = threadIdx.x;
    s[t] = (t < nb) ? bs[t] : 0;
    __syncthreads();
    #pragma unroll
    for (int off = 1; off < 64; off <<= 1) {
        int x = (t >= off) ? s[t - off] : 0;
        __syncthreads();
        s[t] += x;
        __syncthreads();
    }
    if (t < nb) bs[t] = s[t];
}

__global__ void __launch_bounds__(1024) scan3_kernel(
    const int* __restrict__ incl_x, const int* __restrict__ incl_z,
    const int* __restrict__ bsum_x, const int* __restrict__ bsum_z,
    int* __restrict__ offs_x, int* __restrict__ offs_z)
{
    const int* incl = blockIdx.y == 0 ? incl_x : incl_z;
    const int* bsum = blockIdx.y == 0 ? bsum_x : bsum_z;
    int*       offs = blockIdx.y == 0 ? offs_x : offs_z;
    int gid = blockIdx.x * 1024 + threadIdx.x;
    if (gid < NUM_VN) {
        int add = (blockIdx.x > 0) ? bsum[blockIdx.x - 1] : 0;
        offs[gid + 1] = incl[gid] + add;
    }
    if (gid == 0) offs[0] = 0;
}

// ---------------------------------------------------------------------------
// fill CSR payload: pack from-index (15 bits) with syndrome mask (16 bits)
__global__ void __launch_bounds__(256) fill_kernel(
    const int* __restrict__ from_x, const int* __restrict__ to_x,
    const int* __restrict__ from_z, const int* __restrict__ to_z,
    const int* __restrict__ offs_x, const int* __restrict__ offs_z,
    const unsigned* __restrict__ mask_x, const unsigned* __restrict__ mask_z,
    int* __restrict__ cur_x, int* __restrict__ cur_z,
    unsigned* __restrict__ csr_x, unsigned* __restrict__ csr_z)
{
    int e = blockIdx.x * 256 + threadIdx.x;
    if (e >= NUM_E) return;
    {
        int v = __ldg(to_x + e);
        int f = __ldg(from_x + e);
        int p = atomicAdd(&cur_x[v], 1);
        csr_x[__ldg(offs_x + v) + p] = (unsigned)f | (__ldg(mask_x + f) << 16);
    }
    {
        int v = __ldg(to_z + e);
        int f = __ldg(from_z + e);
        int p = atomicAdd(&cur_z[v], 1);
        csr_z[__ldg(offs_z + v) + p] = (unsigned)f | (__ldg(mask_z + f) << 16);
    }
}

// ---------------------------------------------------------------------------
// node partials -> fp16. warp = one n x 4 b; lane = b_local*8 + chunk, owns 4 dims.
__global__ void __launch_bounds__(256) np_kernel(
    const float* __restrict__ hx, const float* __restrict__ hz,
    const float* __restrict__ Wx1, const float* __restrict__ Wz1,
    __half* __restrict__ ox, __half* __restrict__ oz)
{
    const float* h  = blockIdx.y == 0 ? hx  : hz;
    const float* W1 = blockIdx.y == 0 ? Wx1 : Wz1;
    __half*      o  = blockIdx.y == 0 ? ox  : oz;

    __shared__ float4 sW1[128];   // W1 rows 0..15 (16x32)
    int t = threadIdx.x;
    if (t < 128) sW1[t] = reinterpret_cast<const float4*>(W1)[t];
    __syncthreads();

    int wid = t >> 5;
    int unit = blockIdx.x * 8 + wid;          // n*4 + bgroup, < 100000
    int n = unit >> 2;
    int b = ((unit & 3) << 2) | ((t >> 3) & 3);
    int chunk = t & 7;

    const float4* ph = reinterpret_cast<const float4*>(h + ((size_t)b * NUM_CN + n) * D_EMB);
    float4 h0 = ph[0], h1 = ph[1], h2 = ph[2], h3 = ph[3];
    float hr[16] = {h0.x,h0.y,h0.z,h0.w, h1.x,h1.y,h1.z,h1.w,
                    h2.x,h2.y,h2.z,h2.w, h3.x,h3.y,h3.z,h3.w};

    ULL a0 = 0ull, a1 = 0ull;
    #pragma unroll
    for (int d = 0; d < 16; d++) {
        float4 w = sW1[d*8 + chunk];
        ULL hd = pk2(hr[d]);
        a0 = f2fma(hd, pkp(w.x, w.y), a0);
        a1 = f2fma(hd, pkp(w.z, w.w), a1);
    }

    float2 p = up2(a0), q = up2(a1);
    __half2 lo = __float22half2_rn(p);
    __half2 hi = __float22half2_rn(q);
    uint2 st;
    st.x = *reinterpret_cast<unsigned*>(&lo);
    st.y = *reinterpret_cast<unsigned*>(&hi);
    reinterpret_cast<uint2*>(o)[((size_t)n * B_SZ + b) * 8 + chunk] = st;
}

// ---------------------------------------------------------------------------
// fused kernel: per warp-unit (v, 4 consecutive b); lane = b_local*8 + chunk.
//   per pol: hp = h_to[v,b]@W1[16:32] (lane: 4 dims)
//            s  = sum_{edges(v), syn} relu(hf16[f,b] + hp)
//            msg = s@W2 (shfl, lane: 2 dims)
//   vn: hid = relu([mx|mz|htv]@We1) (shfl-broadcast), out = hid@We2 (shfl)
__global__ void __launch_bounds__(256) fused_kernel(
    const float* __restrict__ h_to,
    const __half* __restrict__ hfx, const __half* __restrict__ hfz,
    const int* __restrict__ offs_x, const unsigned* __restrict__ csr_x,
    const int* __restrict__ offs_z, const unsigned* __restrict__ csr_z,
    const float* __restrict__ Wx1, const float* __restrict__ Wz1,
    const float* __restrict__ Wx2, const float* __restrict__ Wz2,
    const float* __restrict__ We1, const float* __restrict__ We2,
    float* __restrict__ out)
{
    // smem: [0,128) W1x rows16-31 | [128,256) W1z | [256,384) Wx2 | [384,512) Wz2
    //       [512,896) We1 | [896,1024) We2     (float4 units, 16KB)
    __shared__ float4 sW[1024];
    int t = threadIdx.x;
    {
        const float4* w1x = reinterpret_cast<const float4*>(Wx1 + 16 * 32);
        const float4* w1z = reinterpret_cast<const float4*>(Wz1 + 16 * 32);
        const float4* w2x = reinterpret_cast<const float4*>(Wx2);
        const float4* w2z = reinterpret_cast<const float4*>(Wz2);
        const float4* we1 = reinterpret_cast<const float4*>(We1);
        const float4* we2 = reinterpret_cast<const float4*>(We2);
        if (t < 128) { sW[t] = w1x[t]; sW[128 + t] = w1z[t]; }
        else if (t < 256) { int i = t - 128; sW[256 + i] = w2x[i]; sW[384 + i] = w2z[i]; }
        for (int i = t; i < 384; i += 256) sW[512 + i] = we1[i];
        if (t >= 128 && t < 256) ;  // we2 below
        if (t < 128) sW[896 + t] = we2[t];
    }
    __syncthreads();

    const ULL* sWx2p = reinterpret_cast<const ULL*>(sW + 256);
    const ULL* sWz2p = reinterpret_cast<const ULL*>(sW + 384);
    const ULL* sWe2p = reinterpret_cast<const ULL*>(sW + 896);

    int wid = t >> 5;
    int unit = blockIdx.x * 8 + wid;          // v*4 + bgroup, < 200000
    int v = unit >> 2;
    int b = ((unit & 3) << 2) | ((t >> 3) & 3);
    int chunk = t & 7;

    // h_to[b][v][0..16]
    float htv[16];
    {
        const float4* ph = reinterpret_cast<const float4*>(
            h_to + ((size_t)b * NUM_VN + v) * D_EMB);
        float4 h0 = ph[0], h1 = ph[1], h2 = ph[2], h3 = ph[3];
        htv[0]=h0.x; htv[1]=h0.y; htv[2]=h0.z; htv[3]=h0.w;
        htv[4]=h1.x; htv[5]=h1.y; htv[6]=h1.z; htv[7]=h1.w;
        htv[8]=h2.x; htv[9]=h2.y; htv[10]=h2.z; htv[11]=h2.w;
        htv[12]=h3.x; htv[13]=h3.y; htv[14]=h3.z; htv[15]=h3.w;
    }

    float sx[4], sz[4];

    #pragma unroll
    for (int pol = 0; pol < 2; pol++) {
        const float4* w1 = sW + (pol ? 128 : 0);
        // hp: lane's 4 hidden dims
        ULL hp0 = 0ull, hp1 = 0ull;
        #pragma unroll
        for (int d = 0; d < 16; d++) {
            float4 w = w1[d*8 + chunk];
            ULL hd = pk2(htv[d]);
            hp0 = f2fma(hd, pkp(w.x, w.y), hp0);
            hp1 = f2fma(hd, pkp(w.z, w.w), hp1);
        }
        float2 hpa = up2(hp0), hpb = up2(hp1);

        const int*      offs = pol ? offs_z : offs_x;
        const unsigned* csr  = pol ? csr_z  : csr_x;
        const uint2*    hf2  = reinterpret_cast<const uint2*>(pol ? hfz : hfx);

        float s0 = 0.f, s1 = 0.f, s2 = 0.f, s3 = 0.f;
        int beg = __ldg(offs + v), end = __ldg(offs + v + 1);
        unsigned pk_n = 0;
        if (beg < end) pk_n = __ldg(csr + beg);
        for (int e = beg; e < end; e++) {
            unsigned pk = pk_n;
            if (e + 1 < end) pk_n = __ldg(csr + e + 1);
            if ((pk >> (16 + b)) & 1u) {
                int f = (int)(pk & 0xFFFFu);
                uint2 hv = hf2[((size_t)f * B_SZ + b) * 8 + chunk];  // 8B/lane, coalesced
                float2 lo = __half22float2(*reinterpret_cast<__half2*>(&hv.x));
                float2 hi = __half22float2(*reinterpret_cast<__half2*>(&hv.y));
                s0 += fmaxf(lo.x + hpa.x, 0.f);
                s1 += fmaxf(lo.y + hpa.y, 0.f);
                s2 += fmaxf(hi.x + hpb.x, 0.f);
                s3 += fmaxf(hi.y + hpb.y, 0.f);
            }
        }
        if (pol == 0) { sx[0]=s0; sx[1]=s1; sx[2]=s2; sx[3]=s3; }
        else          { sz[0]=s0; sz[1]=s1; sz[2]=s2; sz[3]=s3; }
    }

    // msg = s @ W2 per pol: lane computes msg dims 2*chunk, 2*chunk+1
    ULL mxp = 0ull, mzp = 0ull;
    #pragma unroll
    for (int j = 0; j < 32; j++) {
        float sjx = __shfl_sync(0xffffffffu, sx[j & 3], j >> 2, 8);
        float sjz = __shfl_sync(0xffffffffu, sz[j & 3], j >> 2, 8);
        mxp = f2fma(pk2(sjx), sWx2p[j*8 + chunk], mxp);
        mzp = f2fma(pk2(sjz), sWz2p[j*8 + chunk], mzp);
    }
    float2 mx = up2(mxp), mz = up2(mzp);
    float mxv[2] = {mx.x, mx.y};
    float mzv[2] = {mz.x, mz.y};

    // vn GEMM1: hid cols 4*chunk..+4; feat = [mx(16) | mz(16) | htv(16)]
    ULL a0 = 0ull, a1 = 0ull;
    const float4* we1 = sW + 512;
    #pragma unroll
    for (int d = 0; d < 16; d++) {
        float fd = __shfl_sync(0xffffffffu, mxv[d & 1], d >> 1, 8);
        float4 w = we1[d*8 + chunk];
        ULL fdp = pk2(fd);
        a0 = f2fma(fdp, pkp(w.x, w.y), a0);
        a1 = f2fma(fdp, pkp(w.z, w.w), a1);
    }
    #pragma unroll
    for (int d = 0; d < 16; d++) {
        float fd = __shfl_sync(0xffffffffu, mzv[d & 1], d >> 1, 8);
        float4 w = we1[(16 + d)*8 + chunk];
        ULL fdp = pk2(fd);
        a0 = f2fma(fdp, pkp(w.x, w.y), a0);
        a1 = f2fma(fdp, pkp(w.z, w.w), a1);
    }
    #pragma unroll
    for (int d = 0; d < 16; d++) {
        float4 w = we1[(32 + d)*8 + chunk];
        ULL fdp = pk2(htv[d]);
        a0 = f2fma(fdp, pkp(w.x, w.y), a0);
        a1 = f2fma(fdp, pkp(w.z, w.w), a1);
    }
    float2 pa = up2(a0), pb = up2(a1);
    float hid[4] = {fmaxf(pa.x, 0.f), fmaxf(pa.y, 0.f),
                    fmaxf(pb.x, 0.f), fmaxf(pb.y, 0.f)};

    // vn GEMM2: out dims 2*chunk, 2*chunk+1
    ULL o = 0ull;
    #pragma unroll
    for (int j = 0; j < 32; j++) {
        float hj = __shfl_sync(0xffffffffu, hid[j & 3], j >> 2, 8);
        o = f2fma(pk2(hj), sWe2p[j*8 + chunk], o);
    }

    reinterpret_cast<ULL*>(out)[((size_t)b * NUM_VN + v) * 8 + chunk] = o;
}

// ---------------------------------------------------------------------------
extern "C" void kernel_launch(void* const* d_in, const int* in_sizes, int n_in,
                              void* d_out, int out_size) {
    const float* h_from_x   = (const float*)d_in[0];
    const float* h_from_z   = (const float*)d_in[1];
    const float* h_to       = (const float*)d_in[2];
    const int*   syndrome_x = (const int*)d_in[3];
    const int*   syndrome_z = (const int*)d_in[4];
    const int*   from_ind_x = (const int*)d_in[5];
    const int*   to_ind_x   = (const int*)d_in[6];
    const int*   from_ind_z = (const int*)d_in[7];
    const int*   to_ind_z   = (const int*)d_in[8];
    const float* Wx1        = (const float*)d_in[9];
    const float* Wx2        = (const float*)d_in[10];
    const float* Wz1        = (const float*)d_in[11];
    const float* Wz2        = (const float*)d_in[12];
    const float* We1        = (const float*)d_in[13];
    const float* We2        = (const float*)d_in[14];
    float* out = (float*)d_out;

    __half *hf_x, *hf_z;
    int *cnt, *incl_x, *incl_z, *bsum_x, *bsum_z, *offs_x, *offs_z;
    unsigned *csr_x, *csr_z, *mask_x, *mask_z;
    cudaGetSymbolAddress((void**)&hf_x, g_hf_x);
    cudaGetSymbolAddress((void**)&hf_z, g_hf_z);
    cudaGetSymbolAddress((void**)&cnt,  g_cnt);
    cudaGetSymbolAddress((void**)&incl_x, g_incl_x);
    cudaGetSymbolAddress((void**)&incl_z, g_incl_z);
    cudaGetSymbolAddress((void**)&bsum_x, g_bsum_x);
    cudaGetSymbolAddress((void**)&bsum_z, g_bsum_z);
    cudaGetSymbolAddress((void**)&offs_x, g_offs_x);
    cudaGetSymbolAddress((void**)&offs_z, g_offs_z);
    cudaGetSymbolAddress((void**)&csr_x, g_csr_x);
    cudaGetSymbolAddress((void**)&csr_z, g_csr_z);
    cudaGetSymbolAddress((void**)&mask_x, g_mask_x);
    cudaGetSymbolAddress((void**)&mask_z, g_mask_z);

    int *deg_x = cnt, *deg_z = cnt + NUM_VN;
    int *cur_x = cnt + 2 * NUM_VN, *cur_z = cnt + 3 * NUM_VN;

    cudaMemsetAsync(cnt, 0, 4 * NUM_VN * sizeof(int), 0);

    const int SB = (NUM_VN + 1023) / 1024;   // 49

    prep_kernel<<<(NUM_E + 255) / 256, 256>>>(
        to_ind_x, to_ind_z, syndrome_x, syndrome_z,
        deg_x, deg_z, mask_x, mask_z);

    scan1_kernel<<<dim3(SB, 2), 1024>>>(deg_x, deg_z, incl_x, incl_z, bsum_x, bsum_z);
    scan2_kernel<<<2, 64>>>(bsum_x, bsum_z, SB);
    scan3_kernel<<<dim3(SB, 2), 1024>>>(incl_x, incl_z, bsum_x, bsum_z, offs_x, offs_z);

    fill_kernel<<<(NUM_E + 255) / 256, 256>>>(
        from_ind_x, to_ind_x, from_ind_z, to_ind_z,
        offs_x, offs_z, mask_x, mask_z, cur_x, cur_z, csr_x, csr_z);

    // node partials -> fp16: 100000 warp-units per pol
    np_kernel<<<dim3(12500, 2), 256>>>(h_from_x, h_from_z, Wx1, Wz1, hf_x, hf_z);

    // fused message + vertex MLP: 200000 warp-units (both pols inside)
    fused_kernel<<<25000, 256>>>(
        h_to, hf_x, hf_z,
        offs_x, csr_x, offs_z, csr_z,
        Wx1, Wz1, Wx2, Wz2, We1, We2, out);
}

// round 7
// speedup vs baseline: 1.2066x; 1.2066x over previous
#include <cuda_runtime.h>
#include <cuda_fp16.h>

#define B_SZ   16
#define NUM_CN 25000
#define NUM_VN 50000
#define NUM_E  200000
#define D_EMB  16
#define D_HID  32
#define D_MSG  16

typedef unsigned long long ULL;

// ---- scratch (device globals) ----
__device__ __half g_hf_x[(size_t)NUM_CN * B_SZ * D_HID];   // [CN][B][32] fp16
__device__ __half g_hf_z[(size_t)NUM_CN * B_SZ * D_HID];
__device__ __half g_m[(size_t)2 * NUM_VN * B_SZ * D_MSG];  // [pol][v*16+b][16] fp16
__device__ int      g_cnt[4 * NUM_VN];                     // deg_x|deg_z|cur_x|cur_z
__device__ int      g_incl_x[NUM_VN], g_incl_z[NUM_VN];
__device__ int      g_bsum_x[64],     g_bsum_z[64];
__device__ int      g_offs_x[NUM_VN + 1], g_offs_z[NUM_VN + 1];
__device__ unsigned g_csr_x[NUM_E],   g_csr_z[NUM_E];      // f | (mask<<16)
__device__ unsigned g_mask_x[NUM_CN], g_mask_z[NUM_CN];

// ---------------------------------------------------------------------------
// f32x2 packed helpers
__device__ __forceinline__ ULL pk2(float x) {
    ULL d; asm("mov.b64 %0, {%1, %1};" : "=l"(d) : "f"(x)); return d;
}
__device__ __forceinline__ ULL pkp(float x, float y) {
    ULL d; asm("mov.b64 %0, {%1, %2};" : "=l"(d) : "f"(x), "f"(y)); return d;
}
__device__ __forceinline__ float2 up2(ULL a) {
    float lo, hi; asm("mov.b64 {%0, %1}, %2;" : "=f"(lo), "=f"(hi) : "l"(a));
    return make_float2(lo, hi);
}
__device__ __forceinline__ ULL f2fma(ULL a, ULL b, ULL c) {
    ULL d; asm("fma.rn.f32x2 %0, %1, %2, %3;" : "=l"(d) : "l"(a), "l"(b), "l"(c));
    return d;
}
__device__ __forceinline__ float4 mk4(ULL a, ULL b) {
    float2 p = up2(a), q = up2(b);
    return make_float4(p.x, p.y, q.x, q.y);
}

// ---------------------------------------------------------------------------
// kernel 0: degree histogram + syndrome bitmask pack
__global__ void __launch_bounds__(256) prep_kernel(
    const int* __restrict__ to_x, const int* __restrict__ to_z,
    const int* __restrict__ syn_x, const int* __restrict__ syn_z,
    int* __restrict__ deg_x, int* __restrict__ deg_z,
    unsigned* __restrict__ mask_x, unsigned* __restrict__ mask_z)
{
    int i = blockIdx.x * 256 + threadIdx.x;
    if (i < NUM_E) {
        atomicAdd(&deg_x[__ldg(to_x + i)], 1);
        atomicAdd(&deg_z[__ldg(to_z + i)], 1);
    }
    if (i < NUM_CN) {
        unsigned mx = 0, mz = 0;
        #pragma unroll
        for (int b = 0; b < B_SZ; b++) {
            mx |= (unsigned)(__ldg(syn_x + (size_t)b * NUM_CN + i) & 1) << b;
            mz |= (unsigned)(__ldg(syn_z + (size_t)b * NUM_CN + i) & 1) << b;
        }
        mask_x[i] = mx;
        mask_z[i] = mz;
    }
}

// ---------------------------------------------------------------------------
// parallel scan
__global__ void __launch_bounds__(1024) scan1_kernel(
    const int* __restrict__ deg_x, const int* __restrict__ deg_z,
    int* __restrict__ incl_x, int* __restrict__ incl_z,
    int* __restrict__ bsum_x, int* __restrict__ bsum_z)
{
    const int* deg  = blockIdx.y == 0 ? deg_x  : deg_z;
    int*       incl = blockIdx.y == 0 ? incl_x : incl_z;
    int*       bsum = blockIdx.y == 0 ? bsum_x : bsum_z;
    __shared__ int s[1024];
    int t = threadIdx.x;
    int gid = blockIdx.x * 1024 + t;
    s[t] = (gid < NUM_VN) ? deg[gid] : 0;
    __syncthreads();
    #pragma unroll
    for (int off = 1; off < 1024; off <<= 1) {
        int x = (t >= off) ? s[t - off] : 0;
        __syncthreads();
        s[t] += x;
        __syncthreads();
    }
    if (gid < NUM_VN) incl[gid] = s[t];
    if (t == 1023) bsum[blockIdx.x] = s[t];
}

__global__ void __launch_bounds__(64) scan2_kernel(int* bsum_x, int* bsum_z, int nb)
{
    int* bs = blockIdx.x == 0 ? bsum_x : bsum_z;
    __shared__ int s[64];
    int t = threadIdx.x;
    s[t] = (t < nb) ? bs[t] : 0;
    __syncthreads();
    #pragma unroll
    for (int off = 1; off < 64; off <<= 1) {
        int x = (t >= off) ? s[t - off] : 0;
        __syncthreads();
        s[t] += x;
        __syncthreads();
    }
    if (t < nb) bs[t] = s[t];
}

__global__ void __launch_bounds__(1024) scan3_kernel(
    const int* __restrict__ incl_x, const int* __restrict__ incl_z,
    const int* __restrict__ bsum_x, const int* __restrict__ bsum_z,
    int* __restrict__ offs_x, int* __restrict__ offs_z)
{
    const int* incl = blockIdx.y == 0 ? incl_x : incl_z;
    const int* bsum = blockIdx.y == 0 ? bsum_x : bsum_z;
    int*       offs = blockIdx.y == 0 ? offs_x : offs_z;
    int gid = blockIdx.x * 1024 + threadIdx.x;
    if (gid < NUM_VN) {
        int add = (blockIdx.x > 0) ? bsum[blockIdx.x - 1] : 0;
        offs[gid + 1] = incl[gid] + add;
    }
    if (gid == 0) offs[0] = 0;
}

// ---------------------------------------------------------------------------
// fill CSR payload: from-index (16 bits) | syndrome mask (16 bits)
__global__ void __launch_bounds__(256) fill_kernel(
    const int* __restrict__ from_x, const int* __restrict__ to_x,
    const int* __restrict__ from_z, const int* __restrict__ to_z,
    const int* __restrict__ offs_x, const int* __restrict__ offs_z,
    const unsigned* __restrict__ mask_x, const unsigned* __restrict__ mask_z,
    int* __restrict__ cur_x, int* __restrict__ cur_z,
    unsigned* __restrict__ csr_x, unsigned* __restrict__ csr_z)
{
    int e = blockIdx.x * 256 + threadIdx.x;
    if (e >= NUM_E) return;
    {
        int v = __ldg(to_x + e);
        int f = __ldg(from_x + e);
        int p = atomicAdd(&cur_x[v], 1);
        csr_x[__ldg(offs_x + v) + p] = (unsigned)f | (__ldg(mask_x + f) << 16);
    }
    {
        int v = __ldg(to_z + e);
        int f = __ldg(from_z + e);
        int p = atomicAdd(&cur_z[v], 1);
        csr_z[__ldg(offs_z + v) + p] = (unsigned)f | (__ldg(mask_z + f) << 16);
    }
}

// ---------------------------------------------------------------------------
// node partials -> fp16. warp = one n x 4 b; lane = b_local*8 + chunk, owns 4 dims.
__global__ void __launch_bounds__(256) np_kernel(
    const float* __restrict__ hx, const float* __restrict__ hz,
    const float* __restrict__ Wx1, const float* __restrict__ Wz1,
    __half* __restrict__ ox, __half* __restrict__ oz)
{
    const float* h  = blockIdx.y == 0 ? hx  : hz;
    const float* W1 = blockIdx.y == 0 ? Wx1 : Wz1;
    __half*      o  = blockIdx.y == 0 ? ox  : oz;

    __shared__ float4 sW1[128];   // W1 rows 0..15 (16x32)
    int t = threadIdx.x;
    if (t < 128) sW1[t] = reinterpret_cast<const float4*>(W1)[t];
    __syncthreads();

    int wid = t >> 5;
    int unit = blockIdx.x * 8 + wid;          // n*4 + bgroup, < 100000
    int n = unit >> 2;
    int b = ((unit & 3) << 2) | ((t >> 3) & 3);
    int chunk = t & 7;

    const float4* ph = reinterpret_cast<const float4*>(h + ((size_t)b * NUM_CN + n) * D_EMB);
    float4 h0 = ph[0], h1 = ph[1], h2 = ph[2], h3 = ph[3];
    float hr[16] = {h0.x,h0.y,h0.z,h0.w, h1.x,h1.y,h1.z,h1.w,
                    h2.x,h2.y,h2.z,h2.w, h3.x,h3.y,h3.z,h3.w};

    ULL a0 = 0ull, a1 = 0ull;
    #pragma unroll
    for (int d = 0; d < 16; d++) {
        float4 w = sW1[d*8 + chunk];
        ULL hd = pk2(hr[d]);
        a0 = f2fma(hd, pkp(w.x, w.y), a0);
        a1 = f2fma(hd, pkp(w.z, w.w), a1);
    }

    __half2 lo = __float22half2_rn(up2(a0));
    __half2 hi = __float22half2_rn(up2(a1));
    uint2 st;
    st.x = *reinterpret_cast<unsigned*>(&lo);
    st.y = *reinterpret_cast<unsigned*>(&hi);
    reinterpret_cast<uint2*>(o)[((size_t)n * B_SZ + b) * 8 + chunk] = st;
}

// ---------------------------------------------------------------------------
// msg kernel: grid.y = polarity; warp = one v x 4 consecutive b;
// lane = b_local*8 + chunk owns hidden dims 4*chunk..+4.
__global__ void __launch_bounds__(256) msg_kernel(
    const float* __restrict__ h_to,
    const __half* __restrict__ hfx, const __half* __restrict__ hfz,
    const int* __restrict__ offs_x, const unsigned* __restrict__ csr_x,
    const int* __restrict__ offs_z, const unsigned* __restrict__ csr_z,
    const float* __restrict__ Wx1, const float* __restrict__ Wz1,
    const float* __restrict__ Wx2, const float* __restrict__ Wz2,
    __half* __restrict__ m)
{
    int pol = blockIdx.y;
    const uint2*    hf2  = reinterpret_cast<const uint2*>(pol ? hfz : hfx);
    const int*      offs = pol ? offs_z : offs_x;
    const unsigned* csr  = pol ? csr_z  : csr_x;

    __shared__ float4 sW1[128];   // W1 rows 16..31 (16x32)
    __shared__ float  sW2[512];   // W2 (32x16)
    {
        const float4* w1 = reinterpret_cast<const float4*>((pol ? Wz1 : Wx1) + 16 * 32);
        const float4* w2 = reinterpret_cast<const float4*>(pol ? Wz2 : Wx2);
        int t = threadIdx.x;
        if (t < 128) {
            sW1[t] = w1[t];
            reinterpret_cast<float4*>(sW2)[t] = w2[t];
        }
    }
    __syncthreads();

    int t = threadIdx.x;
    int wid = t >> 5;
    int unit = blockIdx.x * 8 + wid;          // v*4 + bgroup, < 200000
    int v = unit >> 2;
    int b = ((unit & 3) << 2) | ((t >> 3) & 3);
    int chunk = t & 7;

    // hp: lane's 4 hidden dims of h_to partial
    ULL hp0 = 0ull, hp1 = 0ull;
    {
        const float4* ph = reinterpret_cast<const float4*>(
            h_to + ((size_t)b * NUM_VN + v) * D_EMB);
        float4 h0 = ph[0], h1 = ph[1], h2 = ph[2], h3 = ph[3];
        float hr[16] = {h0.x,h0.y,h0.z,h0.w, h1.x,h1.y,h1.z,h1.w,
                        h2.x,h2.y,h2.z,h2.w, h3.x,h3.y,h3.z,h3.w};
        #pragma unroll
        for (int d = 0; d < 16; d++) {
            float4 w = sW1[d*8 + chunk];
            ULL hd = pk2(hr[d]);
            hp0 = f2fma(hd, pkp(w.x, w.y), hp0);
            hp1 = f2fma(hd, pkp(w.z, w.w), hp1);
        }
    }
    float2 hpa = up2(hp0), hpb = up2(hp1);

    // edge accumulation (2-wide: two hf loads in flight)
    float s0 = 0.f, s1 = 0.f, s2 = 0.f, s3 = 0.f;
    int beg = __ldg(offs + v), end = __ldg(offs + v + 1);
    unsigned shift = 16 + b;
    for (int e = beg; e < end; e += 2) {
        unsigned pa = __ldg(csr + e);
        unsigned pb = (e + 1 < end) ? __ldg(csr + e + 1) : 0u;
        bool ga = (pa >> shift) & 1u;
        bool gb = (pb >> shift) & 1u;
        uint2 va, vb;
        if (ga) va = hf2[((size_t)(pa & 0xFFFFu) * B_SZ + b) * 8 + chunk];
        if (gb) vb = hf2[((size_t)(pb & 0xFFFFu) * B_SZ + b) * 8 + chunk];
        if (ga) {
            float2 lo = __half22float2(*reinterpret_cast<__half2*>(&va.x));
            float2 hi = __half22float2(*reinterpret_cast<__half2*>(&va.y));
            s0 += fmaxf(lo.x + hpa.x, 0.f);
            s1 += fmaxf(lo.y + hpa.y, 0.f);
            s2 += fmaxf(hi.x + hpb.x, 0.f);
            s3 += fmaxf(hi.y + hpb.y, 0.f);
        }
        if (gb) {
            float2 lo = __half22float2(*reinterpret_cast<__half2*>(&vb.x));
            float2 hi = __half22float2(*reinterpret_cast<__half2*>(&vb.y));
            s0 += fmaxf(lo.x + hpa.x, 0.f);
            s1 += fmaxf(lo.y + hpa.y, 0.f);
            s2 += fmaxf(hi.x + hpb.x, 0.f);
            s3 += fmaxf(hi.y + hpb.y, 0.f);
        }
    }

    // msg = s @ W2 : lane computes msg dims 2*chunk, 2*chunk+1
    const ULL* sW2p = reinterpret_cast<const ULL*>(sW2);
    ULL acc = 0ull;
    float sv[4] = {s0, s1, s2, s3};
    #pragma unroll
    for (int j = 0; j < 32; j++) {
        float sj = __shfl_sync(0xffffffffu, sv[j & 3], j >> 2, 8);
        acc = f2fma(pk2(sj), sW2p[j*8 + chunk], acc);
    }

    // store fp16 msg pair
    __half2 hm = __float22half2_rn(up2(acc));
    int idx = v * B_SZ + b;
    reinterpret_cast<unsigned*>(m)[((size_t)pol * NUM_VN * B_SZ + idx) * 8 + chunk] =
        *reinterpret_cast<unsigned*>(&hm);
}

// ---------------------------------------------------------------------------
// vn kernel: out = relu([m_x|m_z|h_to] @ We1) @ We2, m in fp16
__global__ void __launch_bounds__(256, 2) vn_kernel(
    const __half* __restrict__ m, const float* __restrict__ h_to,
    const float* __restrict__ We1, const float* __restrict__ We2,
    float* __restrict__ out)
{
    __shared__ float4 sW1[384];   // We1 48x32
    __shared__ float4 sW2[128];   // We2 32x16
    int t = threadIdx.x;
    for (int i = t; i < 384; i += 256) sW1[i] = reinterpret_cast<const float4*>(We1)[i];
    if (t < 128) sW2[t] = reinterpret_cast<const float4*>(We2)[t];
    __syncthreads();

    int idx = blockIdx.x * 256 + t;   // idx = v*16 + b
    int v = idx >> 4;
    int b = idx & 15;
    const size_t BVN = (size_t)NUM_VN * B_SZ;

    float feat[48];
    {
        const uint4* px = reinterpret_cast<const uint4*>(m + (size_t)idx * D_MSG);
        const uint4* pz = reinterpret_cast<const uint4*>(m + (BVN + idx) * D_MSG);
        #pragma unroll
        for (int q = 0; q < 2; q++) {
            uint4 a = px[q];
            unsigned w[4] = {a.x, a.y, a.z, a.w};
            #pragma unroll
            for (int k = 0; k < 4; k++) {
                float2 p = __half22float2(*reinterpret_cast<__half2*>(&w[k]));
                feat[q*8 + 2*k + 0] = p.x;
                feat[q*8 + 2*k + 1] = p.y;
            }
        }
        #pragma unroll
        for (int q = 0; q < 2; q++) {
            uint4 a = pz[q];
            unsigned w[4] = {a.x, a.y, a.z, a.w};
            #pragma unroll
            for (int k = 0; k < 4; k++) {
                float2 p = __half22float2(*reinterpret_cast<__half2*>(&w[k]));
                feat[16 + q*8 + 2*k + 0] = p.x;
                feat[16 + q*8 + 2*k + 1] = p.y;
            }
        }
        const float4* ph = reinterpret_cast<const float4*>(
            h_to + ((size_t)b * NUM_VN + v) * D_EMB);
        #pragma unroll
        for (int q = 0; q < 4; q++) {
            float4 a = ph[q];
            feat[32+4*q+0]=a.x; feat[32+4*q+1]=a.y; feat[32+4*q+2]=a.z; feat[32+4*q+3]=a.w;
        }
    }

    ULL acc[16];
    #pragma unroll
    for (int q = 0; q < 16; q++) acc[q] = 0ull;
    #pragma unroll
    for (int d = 0; d < 48; d++) {
        ULL fd = pk2(feat[d]);
        #pragma unroll
        for (int k = 0; k < 8; k++) {
            float4 w = sW1[d*8 + k];
            acc[2*k+0] = f2fma(fd, pkp(w.x, w.y), acc[2*k+0]);
            acc[2*k+1] = f2fma(fd, pkp(w.z, w.w), acc[2*k+1]);
        }
    }

    float hid[32];
    #pragma unroll
    for (int q = 0; q < 16; q++) {
        float2 p = up2(acc[q]);
        hid[2*q+0] = fmaxf(p.x, 0.f);
        hid[2*q+1] = fmaxf(p.y, 0.f);
    }

    ULL o[8];
    #pragma unroll
    for (int q = 0; q < 8; q++) o[q] = 0ull;
    #pragma unroll
    for (int j = 0; j < 32; j++) {
        ULL hj = pk2(hid[j]);
        #pragma unroll
        for (int k = 0; k < 4; k++) {
            float4 w = sW2[j*4 + k];
            o[2*k+0] = f2fma(hj, pkp(w.x, w.y), o[2*k+0]);
            o[2*k+1] = f2fma(hj, pkp(w.z, w.w), o[2*k+1]);
        }
    }

    float4* op = reinterpret_cast<float4*>(out + ((size_t)b * NUM_VN + v) * D_EMB);
    #pragma unroll
    for (int q = 0; q < 4; q++) op[q] = mk4(o[2*q], o[2*q+1]);
}

// ---------------------------------------------------------------------------
extern "C" void kernel_launch(void* const* d_in, const int* in_sizes, int n_in,
                              void* d_out, int out_size) {
    const float* h_from_x   = (const float*)d_in[0];
    const float* h_from_z   = (const float*)d_in[1];
    const float* h_to       = (const float*)d_in[2];
    const int*   syndrome_x = (const int*)d_in[3];
    const int*   syndrome_z = (const int*)d_in[4];
    const int*   from_ind_x = (const int*)d_in[5];
    const int*   to_ind_x   = (const int*)d_in[6];
    const int*   from_ind_z = (const int*)d_in[7];
    const int*   to_ind_z   = (const int*)d_in[8];
    const float* Wx1        = (const float*)d_in[9];
    const float* Wx2        = (const float*)d_in[10];
    const float* Wz1        = (const float*)d_in[11];
    const float* Wz2        = (const float*)d_in[12];
    const float* We1        = (const float*)d_in[13];
    const float* We2        = (const float*)d_in[14];
    float* out = (float*)d_out;

    __half *hf_x, *hf_z, *m;
    int *cnt, *incl_x, *incl_z, *bsum_x, *bsum_z, *offs_x, *offs_z;
    unsigned *csr_x, *csr_z, *mask_x, *mask_z;
    cudaGetSymbolAddress((void**)&hf_x, g_hf_x);
    cudaGetSymbolAddress((void**)&hf_z, g_hf_z);
    cudaGetSymbolAddress((void**)&m,    g_m);
    cudaGetSymbolAddress((void**)&cnt,  g_cnt);
    cudaGetSymbolAddress((void**)&incl_x, g_incl_x);
    cudaGetSymbolAddress((void**)&incl_z, g_incl_z);
    cudaGetSymbolAddress((void**)&bsum_x, g_bsum_x);
    cudaGetSymbolAddress((void**)&bsum_z, g_bsum_z);
    cudaGetSymbolAddress((void**)&offs_x, g_offs_x);
    cudaGetSymbolAddress((void**)&offs_z, g_offs_z);
    cudaGetSymbolAddress((void**)&csr_x, g_csr_x);
    cudaGetSymbolAddress((void**)&csr_z, g_csr_z);
    cudaGetSymbolAddress((void**)&mask_x, g_mask_x);
    cudaGetSymbolAddress((void**)&mask_z, g_mask_z);

    int *deg_x = cnt, *deg_z = cnt + NUM_VN;
    int *cur_x = cnt + 2 * NUM_VN, *cur_z = cnt + 3 * NUM_VN;

    cudaMemsetAsync(cnt, 0, 4 * NUM_VN * sizeof(int), 0);

    const int SB = (NUM_VN + 1023) / 1024;   // 49

    prep_kernel<<<(NUM_E + 255) / 256, 256>>>(
        to_ind_x, to_ind_z, syndrome_x, syndrome_z,
        deg_x, deg_z, mask_x, mask_z);

    scan1_kernel<<<dim3(SB, 2), 1024>>>(deg_x, deg_z, incl_x, incl_z, bsum_x, bsum_z);
    scan2_kernel<<<2, 64>>>(bsum_x, bsum_z, SB);
    scan3_kernel<<<dim3(SB, 2), 1024>>>(incl_x, incl_z, bsum_x, bsum_z, offs_x, offs_z);

    fill_kernel<<<(NUM_E + 255) / 256, 256>>>(
        from_ind_x, to_ind_x, from_ind_z, to_ind_z,
        offs_x, offs_z, mask_x, mask_z, cur_x, cur_z, csr_x, csr_z);

    // node partials -> fp16
    np_kernel<<<dim3(12500, 2), 256>>>(h_from_x, h_from_z, Wx1, Wz1, hf_x, hf_z);

    // messages: 200000 warp-units per pol, 2 pols via grid.y
    msg_kernel<<<dim3(25000, 2), 256>>>(
        h_to, hf_x, hf_z,
        offs_x, csr_x, offs_z, csr_z,
        Wx1, Wz1, Wx2, Wz2, m);

    // vertex MLP
    vn_kernel<<<(NUM_VN * B_SZ) / 256, 256>>>(m, h_to, We1, We2, out);
}